// round 1
// baseline (speedup 1.0000x reference)
#include <cuda_runtime.h>
#include <math.h>

#define D_MODEL   2048
#define Q_LATD    1536
#define KV_LATD   512
#define NUM_HEADS 16
#define HEAD_DIM  128
#define BATCH     2
#define SEQ       2048
#define ROWS      (BATCH * SEQ)      // 4096
#define QK_DIM    256                // head_dim(128) + rope(128)

// ---------------- scratch (device globals; no allocation allowed) ----------
__device__ float g_qlat[ROWS * Q_LATD];                 // q latent
__device__ float g_kvlat[ROWS * KV_LATD];               // kv latent
__device__ float g_qnew[(size_t)ROWS * NUM_HEADS * QK_DIM];   // [b,s,h,256]
__device__ float g_knew[(size_t)ROWS * NUM_HEADS * QK_DIM];   // [b,s,h,256]
__device__ float g_v[(size_t)ROWS * D_MODEL];           // [b,s,h*128]
__device__ float g_attn[(size_t)ROWS * D_MODEL];        // attention output
__device__ float g_qrt[(size_t)ROWS * D_MODEL];         // q_rope pre-rope
__device__ float g_krt[(size_t)ROWS * HEAD_DIM];        // k_rope pre-rope

// ---------------- generic fp32 SGEMM: C[M,N] = A[M,K] @ B[K,N] -------------
// Epilogue column remap: out_col = (c/group)*gstride + (c%group) + goff
// (group=N, gstride=0 -> identity). Optional bias[c].
__global__ void __launch_bounds__(256, 2) sgemm128x128(
    const float* __restrict__ A, const float* __restrict__ B,
    float* __restrict__ C, const float* __restrict__ bias,
    int M, int N, int K, int ldc, int group, int gstride, int goff)
{
    __shared__ float As[16][132];   // transposed A tile, padded
    __shared__ float Bs[16][128];

    const int tid = threadIdx.x;
    const int tx = tid & 15, ty = tid >> 4;
    const int bm = blockIdx.y * 128, bn = blockIdx.x * 128;

    const int arow = tid >> 2;            // 0..63
    const int ac   = (tid & 3) * 4;       // 0,4,8,12
    const int brow = tid >> 5;            // 0..7
    const int bc   = (tid & 31) * 4;      // 0..124

    const float* Aptr = A + (size_t)(bm + arow) * K + ac;
    const float* Bptr = B + (size_t)brow * N + bn + bc;

    float acc[8][8];
#pragma unroll
    for (int i = 0; i < 8; i++)
#pragma unroll
        for (int j = 0; j < 8; j++) acc[i][j] = 0.f;

    const int nk = K >> 4;
    float4 ar0 = *(const float4*)(Aptr);
    float4 ar1 = *(const float4*)(Aptr + (size_t)64 * K);
    float4 br0 = *(const float4*)(Bptr);
    float4 br1 = *(const float4*)(Bptr + (size_t)8 * N);

    for (int kt = 0; kt < nk; kt++) {
        As[ac + 0][arow] = ar0.x; As[ac + 1][arow] = ar0.y;
        As[ac + 2][arow] = ar0.z; As[ac + 3][arow] = ar0.w;
        As[ac + 0][arow + 64] = ar1.x; As[ac + 1][arow + 64] = ar1.y;
        As[ac + 2][arow + 64] = ar1.z; As[ac + 3][arow + 64] = ar1.w;
        *(float4*)&Bs[brow][bc]     = br0;
        *(float4*)&Bs[brow + 8][bc] = br1;
        __syncthreads();

        if (kt + 1 < nk) {
            const float* Ap = Aptr + (kt + 1) * 16;
            ar0 = *(const float4*)(Ap);
            ar1 = *(const float4*)(Ap + (size_t)64 * K);
            const float* Bp = Bptr + (size_t)(kt + 1) * 16 * N;
            br0 = *(const float4*)(Bp);
            br1 = *(const float4*)(Bp + (size_t)8 * N);
        }

#pragma unroll
        for (int k = 0; k < 16; k++) {
            float a[8], b[8];
            *(float4*)&a[0] = *(float4*)&As[k][ty * 8];
            *(float4*)&a[4] = *(float4*)&As[k][ty * 8 + 4];
            *(float4*)&b[0] = *(float4*)&Bs[k][tx * 8];
            *(float4*)&b[4] = *(float4*)&Bs[k][tx * 8 + 4];
#pragma unroll
            for (int i = 0; i < 8; i++)
#pragma unroll
                for (int j = 0; j < 8; j++)
                    acc[i][j] = fmaf(a[i], b[j], acc[i][j]);
        }
        __syncthreads();
    }

#pragma unroll
    for (int i = 0; i < 8; i++) {
        int row = bm + ty * 8 + i;
#pragma unroll
        for (int j = 0; j < 8; j++) {
            int c = bn + tx * 8 + j;
            float v = acc[i][j];
            if (bias) v += bias[c];
            int oc = (c / group) * gstride + (c % group) + goff;
            C[(size_t)row * ldc + oc] = v;
        }
    }
}

// ---------------- rope on q (full 2048 dims), scatter into q_new[...,128:256]
__global__ void rope_q_kernel(const float* __restrict__ in, float* __restrict__ qnew)
{
    int j = blockIdx.x * blockDim.x + threadIdx.x;  // 0..1023
    int row = blockIdx.y;                           // 0..4095
    if (j >= 1024) return;
    int pos = row & (SEQ - 1);
    float inv = powf(10000.0f, -(float)j * (1.0f / 1024.0f));
    float ang = (float)pos * inv;
    float sn, cs;
    sincosf(ang, &sn, &cs);
    float x1 = in[(size_t)row * 2048 + j];
    float x2 = in[(size_t)row * 2048 + j + 1024];
    float o1 = x1 * cs - x2 * sn;
    float o2 = x2 * cs + x1 * sn;
    int c1 = j, c2 = j + 1024;
    qnew[(size_t)row * 4096 + (c1 >> 7) * 256 + (c1 & 127) + 128] = o1;
    qnew[(size_t)row * 4096 + (c2 >> 7) * 256 + (c2 & 127) + 128] = o2;
}

// ---------------- rope on k (128 dims) + broadcast to all 16 heads ---------
__global__ void rope_k_kernel(const float* __restrict__ in, float* __restrict__ knew)
{
    int j = threadIdx.x;          // 0..63
    int row = blockIdx.x;         // 0..4095
    int pos = row & (SEQ - 1);
    float inv = powf(10000.0f, -(float)j * (1.0f / 64.0f));
    float ang = (float)pos * inv;
    float sn, cs;
    sincosf(ang, &sn, &cs);
    float x1 = in[(size_t)row * 128 + j];
    float x2 = in[(size_t)row * 128 + j + 64];
    float o1 = x1 * cs - x2 * sn;
    float o2 = x2 * cs + x1 * sn;
    float* base = knew + (size_t)row * 4096 + 128;
#pragma unroll
    for (int h = 0; h < NUM_HEADS; h++) {
        base[h * 256 + j]      = o1;
        base[h * 256 + j + 64] = o2;
    }
}

// ---------------- flash attention: Bq=64, Bk=64, fp32, online softmax ------
#define DS 68   // padded minor stride for d-major smem tiles

__global__ void __launch_bounds__(256, 1) mla_attention(
    const float* __restrict__ Qn, const float* __restrict__ Kn,
    const float* __restrict__ Vp, float* __restrict__ Op)
{
    extern __shared__ float sm[];
    float* sQ  = sm;                    // [256][DS]  (d-major)
    float* sK  = sQ + 256 * DS;         // [256][DS]
    float* sV  = sK + 256 * DS;         // [64][128]  (k-major)
    float* sS  = sV + 64 * 128;         // [64][DS]
    float* sMx = sS + 64 * DS;
    float* sL  = sMx + 64;
    float* sA  = sL + 64;

    const int tid = threadIdx.x;
    const int qt = blockIdx.x, h = blockIdx.y, b = blockIdx.z;
    const int tx = tid & 15, ty = tid >> 4;
    const int qb = ty * 4, kb = tx * 4, db = tx * 8;

    if (tid < 64) { sMx[tid] = -3.0e38f; sL[tid] = 0.f; }

    // stage Q tile transposed (d-major)
    {
        int lr = tid >> 2;
        int lc0 = tid & 3;
        const float* qrow = Qn + (((size_t)(b * SEQ + qt * 64 + lr)) * NUM_HEADS + h) * QK_DIM;
#pragma unroll
        for (int jj = 0; jj < 16; jj++) {
            int c = (lc0 + jj * 4) * 4;
            float4 v = *(const float4*)&qrow[c];
            sQ[(c + 0) * DS + lr] = v.x; sQ[(c + 1) * DS + lr] = v.y;
            sQ[(c + 2) * DS + lr] = v.z; sQ[(c + 3) * DS + lr] = v.w;
        }
    }

    float o[4][8];
#pragma unroll
    for (int i = 0; i < 4; i++)
#pragma unroll
        for (int j = 0; j < 8; j++) o[i][j] = 0.f;

    __syncthreads();

    for (int kt = 0; kt <= qt; kt++) {
        // stage K tile (transposed) + V tile
        {
            int lr = tid >> 2, lc0 = tid & 3;
            const float* krow = Kn + (((size_t)(b * SEQ + kt * 64 + lr)) * NUM_HEADS + h) * QK_DIM;
#pragma unroll
            for (int jj = 0; jj < 16; jj++) {
                int c = (lc0 + jj * 4) * 4;
                float4 v = *(const float4*)&krow[c];
                sK[(c + 0) * DS + lr] = v.x; sK[(c + 1) * DS + lr] = v.y;
                sK[(c + 2) * DS + lr] = v.z; sK[(c + 3) * DS + lr] = v.w;
            }
            int vr = tid >> 5, vc = (tid & 31) * 4;
#pragma unroll
            for (int p = 0; p < 8; p++) {
                const float* vrow = Vp + (size_t)(b * SEQ + kt * 64 + vr + p * 8) * D_MODEL + h * HEAD_DIM;
                *(float4*)&sV[(vr + p * 8) * 128 + vc] = *(const float4*)&vrow[vc];
            }
        }
        __syncthreads();

        // S = (Q @ K^T) * scale  (4x4 per thread)
        float acc[4][4];
#pragma unroll
        for (int i = 0; i < 4; i++)
#pragma unroll
            for (int j = 0; j < 4; j++) acc[i][j] = 0.f;
#pragma unroll 8
        for (int d = 0; d < QK_DIM; d++) {
            float4 qv = *(const float4*)&sQ[d * DS + qb];
            float4 kv = *(const float4*)&sK[d * DS + kb];
            float qa[4] = {qv.x, qv.y, qv.z, qv.w};
            float ka[4] = {kv.x, kv.y, kv.z, kv.w};
#pragma unroll
            for (int i = 0; i < 4; i++)
#pragma unroll
                for (int j = 0; j < 4; j++)
                    acc[i][j] = fmaf(qa[i], ka[j], acc[i][j]);
        }
        const float scale = 0.0625f;   // 1/sqrt(256)
        const bool diag = (kt == qt);
#pragma unroll
        for (int i = 0; i < 4; i++)
#pragma unroll
            for (int j = 0; j < 4; j++) {
                float v = acc[i][j] * scale;
                if (diag && (kb + j > qb + i)) v = -3.0e38f;
                sS[(qb + i) * DS + kb + j] = v;
            }
        __syncthreads();

        // online softmax stats (one thread per query row)
        if (tid < 64) {
            float* r = &sS[tid * DS];
            float mo = sMx[tid];
            float rm = -3.0e38f;
#pragma unroll 8
            for (int k = 0; k < 64; k++) rm = fmaxf(rm, r[k]);
            float mn = fmaxf(mo, rm);
            float al = __expf(mo - mn);
            float ls = 0.f;
#pragma unroll 8
            for (int k = 0; k < 64; k++) {
                float p = __expf(r[k] - mn);
                r[k] = p;
                ls += p;
            }
            sL[tid] = sL[tid] * al + ls;
            sMx[tid] = mn;
            sA[tid] = al;
        }
        __syncthreads();

        // O = O*alpha + P @ V   (4q x 8d per thread)
        float al[4];
#pragma unroll
        for (int i = 0; i < 4; i++) al[i] = sA[qb + i];
#pragma unroll
        for (int i = 0; i < 4; i++)
#pragma unroll
            for (int j = 0; j < 8; j++) o[i][j] *= al[i];
#pragma unroll 4
        for (int kk = 0; kk < 64; kk++) {
            float pp[4];
#pragma unroll
            for (int i = 0; i < 4; i++) pp[i] = sS[(qb + i) * DS + kk];
            float4 v0 = *(const float4*)&sV[kk * 128 + db];
            float4 v1 = *(const float4*)&sV[kk * 128 + db + 4];
            float vv[8] = {v0.x, v0.y, v0.z, v0.w, v1.x, v1.y, v1.z, v1.w};
#pragma unroll
            for (int i = 0; i < 4; i++)
#pragma unroll
                for (int j = 0; j < 8; j++)
                    o[i][j] = fmaf(pp[i], vv[j], o[i][j]);
        }
        __syncthreads();
    }

    // normalize + write out
#pragma unroll
    for (int i = 0; i < 4; i++) {
        float inv = 1.0f / sL[qb + i];
        int row = qt * 64 + qb + i;
        float* optr = Op + (size_t)(b * SEQ + row) * D_MODEL + h * HEAD_DIM + db;
        float4 r0 = make_float4(o[i][0] * inv, o[i][1] * inv, o[i][2] * inv, o[i][3] * inv);
        float4 r1 = make_float4(o[i][4] * inv, o[i][5] * inv, o[i][6] * inv, o[i][7] * inv);
        *(float4*)&optr[0] = r0;
        *(float4*)&optr[4] = r1;
    }
}

// ---------------------------------------------------------------------------
extern "C" void kernel_launch(void* const* d_in, const int* in_sizes, int n_in,
                              void* d_out, int out_size)
{
    const float* inq  = (const float*)d_in[0];
    const float* ink  = (const float*)d_in[1];
    // d_in[2] (inputs_v) is unused by the reference computation
    const float* Wqd  = (const float*)d_in[3];
    const float* Wkvd = (const float*)d_in[4];
    const float* Wqu  = (const float*)d_in[5];
    const float* Wku  = (const float*)d_in[6];
    const float* Wvu  = (const float*)d_in[7];
    const float* Wqr  = (const float*)d_in[8];
    const float* Wkr  = (const float*)d_in[9];
    const float* Wo   = (const float*)d_in[10];
    const float* bo   = (const float*)d_in[11];
    float* out = (float*)d_out;

    float *qlat, *kvlat, *qnew, *knew, *vbuf, *attn, *qrt, *krt;
    cudaGetSymbolAddress((void**)&qlat,  g_qlat);
    cudaGetSymbolAddress((void**)&kvlat, g_kvlat);
    cudaGetSymbolAddress((void**)&qnew,  g_qnew);
    cudaGetSymbolAddress((void**)&knew,  g_knew);
    cudaGetSymbolAddress((void**)&vbuf,  g_v);
    cudaGetSymbolAddress((void**)&attn,  g_attn);
    cudaGetSymbolAddress((void**)&qrt,   g_qrt);
    cudaGetSymbolAddress((void**)&krt,   g_krt);

    // 1) q_latent = inputs_q @ Wq_down           [4096,1536]
    sgemm128x128<<<dim3(Q_LATD / 128, ROWS / 128), 256>>>(
        inq, Wqd, qlat, nullptr, ROWS, Q_LATD, D_MODEL, Q_LATD, Q_LATD, 0, 0);
    // 2) kv_latent = inputs_k @ Wkv_down         [4096,512]
    sgemm128x128<<<dim3(KV_LATD / 128, ROWS / 128), 256>>>(
        ink, Wkvd, kvlat, nullptr, ROWS, KV_LATD, D_MODEL, KV_LATD, KV_LATD, 0, 0);
    // 3) q_proj -> q_new[..., 0:128] (head-interleaved)
    sgemm128x128<<<dim3(D_MODEL / 128, ROWS / 128), 256>>>(
        qlat, Wqu, qnew, nullptr, ROWS, D_MODEL, Q_LATD, 4096, 128, 256, 0);
    // 4) q_rope pre-projection (contiguous)
    sgemm128x128<<<dim3(D_MODEL / 128, ROWS / 128), 256>>>(
        qlat, Wqr, qrt, nullptr, ROWS, D_MODEL, Q_LATD, D_MODEL, D_MODEL, 0, 0);
    // 5) rope(q) -> q_new[..., 128:256]
    rope_q_kernel<<<dim3(4, ROWS), 256>>>(qrt, qnew);
    // 6) k_proj -> k_new[..., 0:128]
    sgemm128x128<<<dim3(D_MODEL / 128, ROWS / 128), 256>>>(
        kvlat, Wku, knew, nullptr, ROWS, D_MODEL, KV_LATD, 4096, 128, 256, 0);
    // 7) v_proj (contiguous [b,s,h*128])
    sgemm128x128<<<dim3(D_MODEL / 128, ROWS / 128), 256>>>(
        kvlat, Wvu, vbuf, nullptr, ROWS, D_MODEL, KV_LATD, D_MODEL, D_MODEL, 0, 0);
    // 8) k_rope pre-projection [4096,128]
    sgemm128x128<<<dim3(HEAD_DIM / 128, ROWS / 128), 256>>>(
        ink, Wkr, krt, nullptr, ROWS, HEAD_DIM, D_MODEL, HEAD_DIM, HEAD_DIM, 0, 0);
    // 9) rope(k) + broadcast to all heads -> k_new[..., 128:256]
    rope_k_kernel<<<ROWS, 64>>>(krt, knew);

    // 10) causal flash attention
    const int attn_smem = (2 * 256 * DS + 64 * 128 + 64 * DS + 3 * 64) * 4;
    cudaFuncSetAttribute(mla_attention,
                         cudaFuncAttributeMaxDynamicSharedMemorySize, attn_smem);
    mla_attention<<<dim3(SEQ / 64, NUM_HEADS, BATCH), 256, attn_smem>>>(
        qnew, knew, vbuf, attn);

    // 11) final projection + bias
    sgemm128x128<<<dim3(D_MODEL / 128, ROWS / 128), 256>>>(
        attn, Wo, out, bo, ROWS, D_MODEL, D_MODEL, D_MODEL, D_MODEL, 0, 0);
}

// round 2
// speedup vs baseline: 1.0014x; 1.0014x over previous
#include <cuda_runtime.h>
#include <math.h>

#define D_MODEL   2048
#define Q_LATD    1536
#define KV_LATD   512
#define NUM_HEADS 16
#define HEAD_DIM  128
#define BATCH     2
#define SEQ       2048
#define ROWS      (BATCH * SEQ)      // 4096
#define QK_DIM    256                // head_dim(128) + rope(128)

// ---------------- scratch (device globals; no allocation allowed) ----------
__device__ float g_qlat[ROWS * Q_LATD];                 // q latent
__device__ float g_kvlat[ROWS * KV_LATD];               // kv latent
__device__ float g_qnew[(size_t)ROWS * NUM_HEADS * QK_DIM];   // [b,s,h,256]
__device__ float g_knew[(size_t)ROWS * NUM_HEADS * QK_DIM];   // [b,s,h,256]
__device__ float g_v[(size_t)ROWS * D_MODEL];           // [b,s,h*128]
__device__ float g_attn[(size_t)ROWS * D_MODEL];        // attention output
__device__ float g_qrt[(size_t)ROWS * D_MODEL];         // q_rope pre-rope
__device__ float g_krt[(size_t)ROWS * HEAD_DIM];        // k_rope pre-rope

// ---------------- generic fp32 SGEMM: C[M,N] = A[M,K] @ B[K,N] -------------
// Epilogue column remap: out_col = (c/group)*gstride + (c%group) + goff
// (group=N, gstride=0 -> identity). Optional bias[c].
__global__ void __launch_bounds__(256, 2) sgemm128x128(
    const float* __restrict__ A, const float* __restrict__ B,
    float* __restrict__ C, const float* __restrict__ bias,
    int M, int N, int K, int ldc, int group, int gstride, int goff)
{
    __shared__ float As[16][132];   // transposed A tile, padded
    __shared__ float Bs[16][128];

    const int tid = threadIdx.x;
    const int tx = tid & 15, ty = tid >> 4;
    const int bm = blockIdx.y * 128, bn = blockIdx.x * 128;

    const int arow = tid >> 2;            // 0..63
    const int ac   = (tid & 3) * 4;       // 0,4,8,12
    const int brow = tid >> 5;            // 0..7
    const int bc   = (tid & 31) * 4;      // 0..124

    const float* Aptr = A + (size_t)(bm + arow) * K + ac;
    const float* Bptr = B + (size_t)brow * N + bn + bc;

    float acc[8][8];
#pragma unroll
    for (int i = 0; i < 8; i++)
#pragma unroll
        for (int j = 0; j < 8; j++) acc[i][j] = 0.f;

    const int nk = K >> 4;
    float4 ar0 = *(const float4*)(Aptr);
    float4 ar1 = *(const float4*)(Aptr + (size_t)64 * K);
    float4 br0 = *(const float4*)(Bptr);
    float4 br1 = *(const float4*)(Bptr + (size_t)8 * N);

    for (int kt = 0; kt < nk; kt++) {
        As[ac + 0][arow] = ar0.x; As[ac + 1][arow] = ar0.y;
        As[ac + 2][arow] = ar0.z; As[ac + 3][arow] = ar0.w;
        As[ac + 0][arow + 64] = ar1.x; As[ac + 1][arow + 64] = ar1.y;
        As[ac + 2][arow + 64] = ar1.z; As[ac + 3][arow + 64] = ar1.w;
        *(float4*)&Bs[brow][bc]     = br0;
        *(float4*)&Bs[brow + 8][bc] = br1;
        __syncthreads();

        if (kt + 1 < nk) {
            const float* Ap = Aptr + (kt + 1) * 16;
            ar0 = *(const float4*)(Ap);
            ar1 = *(const float4*)(Ap + (size_t)64 * K);
            const float* Bp = Bptr + (size_t)(kt + 1) * 16 * N;
            br0 = *(const float4*)(Bp);
            br1 = *(const float4*)(Bp + (size_t)8 * N);
        }

#pragma unroll
        for (int k = 0; k < 16; k++) {
            float a[8], b[8];
            *(float4*)&a[0] = *(float4*)&As[k][ty * 8];
            *(float4*)&a[4] = *(float4*)&As[k][ty * 8 + 4];
            *(float4*)&b[0] = *(float4*)&Bs[k][tx * 8];
            *(float4*)&b[4] = *(float4*)&Bs[k][tx * 8 + 4];
#pragma unroll
            for (int i = 0; i < 8; i++)
#pragma unroll
                for (int j = 0; j < 8; j++)
                    acc[i][j] = fmaf(a[i], b[j], acc[i][j]);
        }
        __syncthreads();
    }

#pragma unroll
    for (int i = 0; i < 8; i++) {
        int row = bm + ty * 8 + i;
#pragma unroll
        for (int j = 0; j < 8; j++) {
            int c = bn + tx * 8 + j;
            float v = acc[i][j];
            if (bias) v += bias[c];
            int oc = (c / group) * gstride + (c % group) + goff;
            C[(size_t)row * ldc + oc] = v;
        }
    }
}

// ---------------- rope on q (full 2048 dims), scatter into q_new[...,128:256]
__global__ void rope_q_kernel(const float* __restrict__ in, float* __restrict__ qnew)
{
    int j = blockIdx.x * blockDim.x + threadIdx.x;  // 0..1023
    int row = blockIdx.y;                           // 0..4095
    if (j >= 1024) return;
    int pos = row & (SEQ - 1);
    float inv = powf(10000.0f, -(float)j * (1.0f / 1024.0f));
    float ang = (float)pos * inv;
    float sn, cs;
    sincosf(ang, &sn, &cs);
    float x1 = in[(size_t)row * 2048 + j];
    float x2 = in[(size_t)row * 2048 + j + 1024];
    float o1 = x1 * cs - x2 * sn;
    float o2 = x2 * cs + x1 * sn;
    int c1 = j, c2 = j + 1024;
    qnew[(size_t)row * 4096 + (c1 >> 7) * 256 + (c1 & 127) + 128] = o1;
    qnew[(size_t)row * 4096 + (c2 >> 7) * 256 + (c2 & 127) + 128] = o2;
}

// ---------------- rope on k (128 dims) + broadcast to all 16 heads ---------
__global__ void rope_k_kernel(const float* __restrict__ in, float* __restrict__ knew)
{
    int j = threadIdx.x;          // 0..63
    int row = blockIdx.x;         // 0..4095
    int pos = row & (SEQ - 1);
    float inv = powf(10000.0f, -(float)j * (1.0f / 64.0f));
    float ang = (float)pos * inv;
    float sn, cs;
    sincosf(ang, &sn, &cs);
    float x1 = in[(size_t)row * 128 + j];
    float x2 = in[(size_t)row * 128 + j + 64];
    float o1 = x1 * cs - x2 * sn;
    float o2 = x2 * cs + x1 * sn;
    float* base = knew + (size_t)row * 4096 + 128;
#pragma unroll
    for (int h = 0; h < NUM_HEADS; h++) {
        base[h * 256 + j]      = o1;
        base[h * 256 + j + 64] = o2;
    }
}

// ---------------- flash attention: Bq=64, Bk=64, fp32, online softmax ------
#define DS 68   // padded minor stride for d-major smem tiles

__global__ void __launch_bounds__(256, 1) mla_attention(
    const float* __restrict__ Qn, const float* __restrict__ Kn,
    const float* __restrict__ Vp, float* __restrict__ Op)
{
    extern __shared__ float sm[];
    float* sQ  = sm;                    // [256][DS]  (d-major)
    float* sK  = sQ + 256 * DS;         // [256][DS]
    float* sV  = sK + 256 * DS;         // [64][128]  (k-major)
    float* sS  = sV + 64 * 128;         // [64][DS]
    float* sMx = sS + 64 * DS;
    float* sL  = sMx + 64;
    float* sA  = sL + 64;

    const int tid = threadIdx.x;
    const int qt = blockIdx.x, h = blockIdx.y, b = blockIdx.z;
    const int tx = tid & 15, ty = tid >> 4;
    const int qb = ty * 4, kb = tx * 4, db = tx * 8;

    if (tid < 64) { sMx[tid] = -3.0e38f; sL[tid] = 0.f; }

    // stage Q tile transposed (d-major)
    {
        int lr = tid >> 2;
        int lc0 = tid & 3;
        const float* qrow = Qn + (((size_t)(b * SEQ + qt * 64 + lr)) * NUM_HEADS + h) * QK_DIM;
#pragma unroll
        for (int jj = 0; jj < 16; jj++) {
            int c = (lc0 + jj * 4) * 4;
            float4 v = *(const float4*)&qrow[c];
            sQ[(c + 0) * DS + lr] = v.x; sQ[(c + 1) * DS + lr] = v.y;
            sQ[(c + 2) * DS + lr] = v.z; sQ[(c + 3) * DS + lr] = v.w;
        }
    }

    float o[4][8];
#pragma unroll
    for (int i = 0; i < 4; i++)
#pragma unroll
        for (int j = 0; j < 8; j++) o[i][j] = 0.f;

    __syncthreads();

    for (int kt = 0; kt <= qt; kt++) {
        // stage K tile (transposed) + V tile
        {
            int lr = tid >> 2, lc0 = tid & 3;
            const float* krow = Kn + (((size_t)(b * SEQ + kt * 64 + lr)) * NUM_HEADS + h) * QK_DIM;
#pragma unroll
            for (int jj = 0; jj < 16; jj++) {
                int c = (lc0 + jj * 4) * 4;
                float4 v = *(const float4*)&krow[c];
                sK[(c + 0) * DS + lr] = v.x; sK[(c + 1) * DS + lr] = v.y;
                sK[(c + 2) * DS + lr] = v.z; sK[(c + 3) * DS + lr] = v.w;
            }
            int vr = tid >> 5, vc = (tid & 31) * 4;
#pragma unroll
            for (int p = 0; p < 8; p++) {
                const float* vrow = Vp + (size_t)(b * SEQ + kt * 64 + vr + p * 8) * D_MODEL + h * HEAD_DIM;
                *(float4*)&sV[(vr + p * 8) * 128 + vc] = *(const float4*)&vrow[vc];
            }
        }
        __syncthreads();

        // S = (Q @ K^T) * scale  (4x4 per thread)
        float acc[4][4];
#pragma unroll
        for (int i = 0; i < 4; i++)
#pragma unroll
            for (int j = 0; j < 4; j++) acc[i][j] = 0.f;
#pragma unroll 8
        for (int d = 0; d < QK_DIM; d++) {
            float4 qv = *(const float4*)&sQ[d * DS + qb];
            float4 kv = *(const float4*)&sK[d * DS + kb];
            float qa[4] = {qv.x, qv.y, qv.z, qv.w};
            float ka[4] = {kv.x, kv.y, kv.z, kv.w};
#pragma unroll
            for (int i = 0; i < 4; i++)
#pragma unroll
                for (int j = 0; j < 4; j++)
                    acc[i][j] = fmaf(qa[i], ka[j], acc[i][j]);
        }
        const float scale = 0.0625f;   // 1/sqrt(256)
        const bool diag = (kt == qt);
#pragma unroll
        for (int i = 0; i < 4; i++)
#pragma unroll
            for (int j = 0; j < 4; j++) {
                float v = acc[i][j] * scale;
                if (diag && (kb + j > qb + i)) v = -3.0e38f;
                sS[(qb + i) * DS + kb + j] = v;
            }
        __syncthreads();

        // online softmax stats (one thread per query row)
        if (tid < 64) {
            float* r = &sS[tid * DS];
            float mo = sMx[tid];
            float rm = -3.0e38f;
#pragma unroll 8
            for (int k = 0; k < 64; k++) rm = fmaxf(rm, r[k]);
            float mn = fmaxf(mo, rm);
            float al = __expf(mo - mn);
            float ls = 0.f;
#pragma unroll 8
            for (int k = 0; k < 64; k++) {
                float p = __expf(r[k] - mn);
                r[k] = p;
                ls += p;
            }
            sL[tid] = sL[tid] * al + ls;
            sMx[tid] = mn;
            sA[tid] = al;
        }
        __syncthreads();

        // O = O*alpha + P @ V   (4q x 8d per thread)
        float al[4];
#pragma unroll
        for (int i = 0; i < 4; i++) al[i] = sA[qb + i];
#pragma unroll
        for (int i = 0; i < 4; i++)
#pragma unroll
            for (int j = 0; j < 8; j++) o[i][j] *= al[i];
#pragma unroll 4
        for (int kk = 0; kk < 64; kk++) {
            float pp[4];
#pragma unroll
            for (int i = 0; i < 4; i++) pp[i] = sS[(qb + i) * DS + kk];
            float4 v0 = *(const float4*)&sV[kk * 128 + db];
            float4 v1 = *(const float4*)&sV[kk * 128 + db + 4];
            float vv[8] = {v0.x, v0.y, v0.z, v0.w, v1.x, v1.y, v1.z, v1.w};
#pragma unroll
            for (int i = 0; i < 4; i++)
#pragma unroll
                for (int j = 0; j < 8; j++)
                    o[i][j] = fmaf(pp[i], vv[j], o[i][j]);
        }
        __syncthreads();
    }

    // normalize + write out
#pragma unroll
    for (int i = 0; i < 4; i++) {
        float inv = 1.0f / sL[qb + i];
        int row = qt * 64 + qb + i;
        float* optr = Op + (size_t)(b * SEQ + row) * D_MODEL + h * HEAD_DIM + db;
        float4 r0 = make_float4(o[i][0] * inv, o[i][1] * inv, o[i][2] * inv, o[i][3] * inv);
        float4 r1 = make_float4(o[i][4] * inv, o[i][5] * inv, o[i][6] * inv, o[i][7] * inv);
        *(float4*)&optr[0] = r0;
        *(float4*)&optr[4] = r1;
    }
}

// ---------------------------------------------------------------------------
extern "C" void kernel_launch(void* const* d_in, const int* in_sizes, int n_in,
                              void* d_out, int out_size)
{
    const float* inq  = (const float*)d_in[0];
    const float* ink  = (const float*)d_in[1];
    // d_in[2] (inputs_v) is unused by the reference computation
    const float* Wqd  = (const float*)d_in[3];
    const float* Wkvd = (const float*)d_in[4];
    const float* Wqu  = (const float*)d_in[5];
    const float* Wku  = (const float*)d_in[6];
    const float* Wvu  = (const float*)d_in[7];
    const float* Wqr  = (const float*)d_in[8];
    const float* Wkr  = (const float*)d_in[9];
    const float* Wo   = (const float*)d_in[10];
    const float* bo   = (const float*)d_in[11];
    float* out = (float*)d_out;

    float *qlat, *kvlat, *qnew, *knew, *vbuf, *attn, *qrt, *krt;
    cudaGetSymbolAddress((void**)&qlat,  g_qlat);
    cudaGetSymbolAddress((void**)&kvlat, g_kvlat);
    cudaGetSymbolAddress((void**)&qnew,  g_qnew);
    cudaGetSymbolAddress((void**)&knew,  g_knew);
    cudaGetSymbolAddress((void**)&vbuf,  g_v);
    cudaGetSymbolAddress((void**)&attn,  g_attn);
    cudaGetSymbolAddress((void**)&qrt,   g_qrt);
    cudaGetSymbolAddress((void**)&krt,   g_krt);

    // 1) q_latent = inputs_q @ Wq_down           [4096,1536]
    sgemm128x128<<<dim3(Q_LATD / 128, ROWS / 128), 256>>>(
        inq, Wqd, qlat, nullptr, ROWS, Q_LATD, D_MODEL, Q_LATD, Q_LATD, 0, 0);
    // 2) kv_latent = inputs_k @ Wkv_down         [4096,512]
    sgemm128x128<<<dim3(KV_LATD / 128, ROWS / 128), 256>>>(
        ink, Wkvd, kvlat, nullptr, ROWS, KV_LATD, D_MODEL, KV_LATD, KV_LATD, 0, 0);
    // 3) q_proj -> q_new[..., 0:128] (head-interleaved)
    sgemm128x128<<<dim3(D_MODEL / 128, ROWS / 128), 256>>>(
        qlat, Wqu, qnew, nullptr, ROWS, D_MODEL, Q_LATD, 4096, 128, 256, 0);
    // 4) q_rope pre-projection (contiguous)
    sgemm128x128<<<dim3(D_MODEL / 128, ROWS / 128), 256>>>(
        qlat, Wqr, qrt, nullptr, ROWS, D_MODEL, Q_LATD, D_MODEL, D_MODEL, 0, 0);
    // 5) rope(q) -> q_new[..., 128:256]
    rope_q_kernel<<<dim3(4, ROWS), 256>>>(qrt, qnew);
    // 6) k_proj -> k_new[..., 0:128]
    sgemm128x128<<<dim3(D_MODEL / 128, ROWS / 128), 256>>>(
        kvlat, Wku, knew, nullptr, ROWS, D_MODEL, KV_LATD, 4096, 128, 256, 0);
    // 7) v_proj (contiguous [b,s,h*128])
    sgemm128x128<<<dim3(D_MODEL / 128, ROWS / 128), 256>>>(
        kvlat, Wvu, vbuf, nullptr, ROWS, D_MODEL, KV_LATD, D_MODEL, D_MODEL, 0, 0);
    // 8) k_rope pre-projection [4096,128]
    sgemm128x128<<<dim3(HEAD_DIM / 128, ROWS / 128), 256>>>(
        ink, Wkr, krt, nullptr, ROWS, HEAD_DIM, D_MODEL, HEAD_DIM, HEAD_DIM, 0, 0);
    // 9) rope(k) + broadcast to all heads -> k_new[..., 128:256]
    rope_k_kernel<<<ROWS, 64>>>(krt, knew);

    // 10) causal flash attention
    const int attn_smem = (2 * 256 * DS + 64 * 128 + 64 * DS + 3 * 64) * 4;
    cudaFuncSetAttribute(mla_attention,
                         cudaFuncAttributeMaxDynamicSharedMemorySize, attn_smem);
    mla_attention<<<dim3(SEQ / 64, NUM_HEADS, BATCH), 256, attn_smem>>>(
        qnew, knew, vbuf, attn);

    // 11) final projection + bias
    sgemm128x128<<<dim3(D_MODEL / 128, ROWS / 128), 256>>>(
        attn, Wo, out, bo, ROWS, D_MODEL, D_MODEL, D_MODEL, D_MODEL, 0, 0);
}

// round 3
// speedup vs baseline: 2.0971x; 2.0941x over previous
#include <cuda_runtime.h>
#include <math.h>
#include <stdint.h>

#define D_MODEL   2048
#define Q_LATD    1536
#define KV_LATD   512
#define NUM_HEADS 16
#define HEAD_DIM  128
#define BATCH     2
#define SEQ       2048
#define ROWS      (BATCH * SEQ)      // 4096
#define QK_DIM    256                // head_dim(128) + rope(128)

// ---------------- scratch (device globals; no allocation allowed) ----------
__device__ float g_qlat[ROWS * Q_LATD];
__device__ float g_kvlat[ROWS * KV_LATD];
__device__ float g_qnew[(size_t)ROWS * NUM_HEADS * QK_DIM];   // [b,s,h,256]
__device__ float g_knew[(size_t)ROWS * NUM_HEADS * QK_DIM];   // [b,s,h,256]
__device__ float g_v[(size_t)ROWS * D_MODEL];                 // [b,s,h*128]
__device__ float g_attn[(size_t)ROWS * D_MODEL];
__device__ float g_qrt[(size_t)ROWS * D_MODEL];
__device__ float g_krt[(size_t)ROWS * HEAD_DIM];

// ---------------- helpers --------------------------------------------------
__device__ __forceinline__ uint32_t f2tf(float x) {
    uint32_t u;
    asm("cvt.rna.tf32.f32 %0, %1;" : "=r"(u) : "f"(x));
    return u;
}

__device__ __forceinline__ void mma8(float c[4],
    uint32_t a0, uint32_t a1, uint32_t a2, uint32_t a3,
    uint32_t b0, uint32_t b1)
{
    asm volatile(
        "mma.sync.aligned.m16n8k8.row.col.f32.tf32.tf32.f32 "
        "{%0,%1,%2,%3}, {%4,%5,%6,%7}, {%8,%9}, {%0,%1,%2,%3};\n"
        : "+f"(c[0]), "+f"(c[1]), "+f"(c[2]), "+f"(c[3])
        : "r"(a0), "r"(a1), "r"(a2), "r"(a3), "r"(b0), "r"(b1));
}

// exp(x) for x <= 0 on the FMA pipe only (no MUFU)
__device__ __forceinline__ float fast_exp(float x) {
    float y  = fmaxf(x * 1.4426950408889634f, -126.0f);
    float tb = y + 12582912.0f;          // round-to-nearest int via 1.5*2^23
    float nf = tb - 12582912.0f;
    float u  = (y - nf) * 0.6931471805599453f;
    float p  = fmaf(u, 0.008333334f, 0.041666668f);
    p = fmaf(p, u, 0.16666667f);
    p = fmaf(p, u, 0.5f);
    p = fmaf(p, u, 1.0f);
    p = fmaf(p, u, 1.0f);
    return p * __int_as_float(((int)nf + 127) << 23);
}

// ---------------- tf32 GEMM: C[M,N] = A[M,K] @ B[K,N] ----------------------
// block 128x128, BK=16, 256 thr / 8 warps, warp tile 64x32, double-buffered.
// Epilogue col remap: oc = (c/group)*gstride + c%group + goff. Optional bias.
__global__ void __launch_bounds__(256, 2) tf32gemm(
    const float* __restrict__ A, const float* __restrict__ B,
    float* __restrict__ C, const float* __restrict__ bias,
    int M, int N, int K, int ldc, int group, int gstride, int goff)
{
    __shared__ uint32_t As[2][16][136];   // [k][m], 136 % 32 == 8
    __shared__ uint32_t Bs[2][16][136];   // [k][n]

    const int tid  = threadIdx.x;
    const int lane = tid & 31, w = tid >> 5;
    const int g = lane >> 2, t = lane & 3;
    const int wm = (w & 1) * 64, wn = (w >> 1) * 32;
    const int bm = blockIdx.y * 128, bn = blockIdx.x * 128;

    const int am = tid >> 1, ak = (tid & 1) * 8;     // A stage: row, k-half
    const int bk = tid >> 4, bn0 = (tid & 15) * 8;   // B stage: k-row, col
    const float* Ag = A + (size_t)(bm + am) * K + ak;
    const float* Bg = B + (size_t)bk * N + bn + bn0;

    float acc[4][4][4];
#pragma unroll
    for (int i = 0; i < 4; i++)
#pragma unroll
        for (int j = 0; j < 4; j++)
#pragma unroll
            for (int e = 0; e < 4; e++) acc[i][j][e] = 0.f;

    const int nk = K >> 4;

    float4 ra0 = *(const float4*)Ag;
    float4 ra1 = *(const float4*)(Ag + 4);
    float4 rb0 = *(const float4*)Bg;
    float4 rb1 = *(const float4*)(Bg + 4);

    As[0][ak + 0][am] = f2tf(ra0.x); As[0][ak + 1][am] = f2tf(ra0.y);
    As[0][ak + 2][am] = f2tf(ra0.z); As[0][ak + 3][am] = f2tf(ra0.w);
    As[0][ak + 4][am] = f2tf(ra1.x); As[0][ak + 5][am] = f2tf(ra1.y);
    As[0][ak + 6][am] = f2tf(ra1.z); As[0][ak + 7][am] = f2tf(ra1.w);
    *(uint4*)&Bs[0][bk][bn0] =
        make_uint4(f2tf(rb0.x), f2tf(rb0.y), f2tf(rb0.z), f2tf(rb0.w));
    *(uint4*)&Bs[0][bk][bn0 + 4] =
        make_uint4(f2tf(rb1.x), f2tf(rb1.y), f2tf(rb1.z), f2tf(rb1.w));

    if (nk > 1) {
        ra0 = *(const float4*)(Ag + 16);
        ra1 = *(const float4*)(Ag + 20);
        rb0 = *(const float4*)(Bg + (size_t)16 * N);
        rb1 = *(const float4*)(Bg + (size_t)16 * N + 4);
    }
    __syncthreads();

    for (int kt = 0; kt < nk; kt++) {
        const int cur = kt & 1;
#pragma unroll
        for (int ks = 0; ks < 2; ks++) {
            const int k0 = ks * 8;
            uint32_t af[4][4], bf[4][2];
#pragma unroll
            for (int mt = 0; mt < 4; mt++) {
                const int m = wm + mt * 16 + g;
                af[mt][0] = As[cur][k0 + t][m];
                af[mt][1] = As[cur][k0 + t][m + 8];
                af[mt][2] = As[cur][k0 + t + 4][m];
                af[mt][3] = As[cur][k0 + t + 4][m + 8];
            }
#pragma unroll
            for (int nt = 0; nt < 4; nt++) {
                const int n = wn + nt * 8 + g;
                bf[nt][0] = Bs[cur][k0 + t][n];
                bf[nt][1] = Bs[cur][k0 + t + 4][n];
            }
#pragma unroll
            for (int mt = 0; mt < 4; mt++)
#pragma unroll
                for (int nt = 0; nt < 4; nt++)
                    mma8(acc[mt][nt], af[mt][0], af[mt][1], af[mt][2], af[mt][3],
                         bf[nt][0], bf[nt][1]);
        }
        if (kt + 1 < nk) {
            const int nxt = cur ^ 1;
            As[nxt][ak + 0][am] = f2tf(ra0.x); As[nxt][ak + 1][am] = f2tf(ra0.y);
            As[nxt][ak + 2][am] = f2tf(ra0.z); As[nxt][ak + 3][am] = f2tf(ra0.w);
            As[nxt][ak + 4][am] = f2tf(ra1.x); As[nxt][ak + 5][am] = f2tf(ra1.y);
            As[nxt][ak + 6][am] = f2tf(ra1.z); As[nxt][ak + 7][am] = f2tf(ra1.w);
            *(uint4*)&Bs[nxt][bk][bn0] =
                make_uint4(f2tf(rb0.x), f2tf(rb0.y), f2tf(rb0.z), f2tf(rb0.w));
            *(uint4*)&Bs[nxt][bk][bn0 + 4] =
                make_uint4(f2tf(rb1.x), f2tf(rb1.y), f2tf(rb1.z), f2tf(rb1.w));
            if (kt + 2 < nk) {
                const float* Ap = Ag + (kt + 2) * 16;
                ra0 = *(const float4*)Ap;
                ra1 = *(const float4*)(Ap + 4);
                const float* Bp = Bg + (size_t)(kt + 2) * 16 * N;
                rb0 = *(const float4*)Bp;
                rb1 = *(const float4*)(Bp + 4);
            }
        }
        __syncthreads();
    }

#pragma unroll
    for (int mt = 0; mt < 4; mt++) {
#pragma unroll
        for (int nt = 0; nt < 4; nt++) {
            const int r = bm + wm + mt * 16 + g;
            const int c = bn + wn + nt * 8 + 2 * t;
#pragma unroll
            for (int e = 0; e < 4; e++) {
                const int rr = r + ((e >> 1) << 3);
                const int cc = c + (e & 1);
                float v = acc[mt][nt][e];
                if (bias) v += bias[cc];
                const int oc = (cc / group) * gstride + (cc % group) + goff;
                C[(size_t)rr * ldc + oc] = v;
            }
        }
    }
}

// ---------------- rope on q (full 2048 dims) -> q_new[...,128:256] ---------
__global__ void rope_q_kernel(const float* __restrict__ in, float* __restrict__ qnew)
{
    int j = blockIdx.x * blockDim.x + threadIdx.x;
    int row = blockIdx.y;
    if (j >= 1024) return;
    int pos = row & (SEQ - 1);
    float inv = powf(10000.0f, -(float)j * (1.0f / 1024.0f));
    float ang = (float)pos * inv;
    float sn, cs;
    sincosf(ang, &sn, &cs);
    float x1 = in[(size_t)row * 2048 + j];
    float x2 = in[(size_t)row * 2048 + j + 1024];
    float o1 = x1 * cs - x2 * sn;
    float o2 = x2 * cs + x1 * sn;
    int c1 = j, c2 = j + 1024;
    qnew[(size_t)row * 4096 + (c1 >> 7) * 256 + (c1 & 127) + 128] = o1;
    qnew[(size_t)row * 4096 + (c2 >> 7) * 256 + (c2 & 127) + 128] = o2;
}

// ---------------- rope on k (128 dims) + broadcast to all 16 heads ---------
__global__ void rope_k_kernel(const float* __restrict__ in, float* __restrict__ knew)
{
    int j = threadIdx.x;
    int row = blockIdx.x;
    int pos = row & (SEQ - 1);
    float inv = powf(10000.0f, -(float)j * (1.0f / 64.0f));
    float ang = (float)pos * inv;
    float sn, cs;
    sincosf(ang, &sn, &cs);
    float x1 = in[(size_t)row * 128 + j];
    float x2 = in[(size_t)row * 128 + j + 64];
    float o1 = x1 * cs - x2 * sn;
    float o2 = x2 * cs + x1 * sn;
    float* base = knew + (size_t)row * 4096 + 128;
#pragma unroll
    for (int h = 0; h < NUM_HEADS; h++) {
        base[h * 256 + j]      = o1;
        base[h * 256 + j + 64] = o2;
    }
}

// ---------------- flash attention, tf32 mma, Bq=Bk=64, 128 threads ---------
#define SQS 260   // % 32 == 4 -> conflict-free 4g+t frag access
#define SVS 136   // % 32 == 8 -> conflict-free 8t+g frag access
#define SPS 68    // % 32 == 4
#define ATT_SMEM_BYTES ((64 * SQS * 2 + 64 * SVS + 64 * SPS) * 4)

__global__ void __launch_bounds__(128, 1) mla_attn_tf32(
    const float* __restrict__ Qn, const float* __restrict__ Kn,
    const float* __restrict__ Vp, float* __restrict__ Op)
{
    extern __shared__ uint32_t sw[];
    uint32_t* sQ = sw;                    // [64][SQS] q-major
    uint32_t* sK = sQ + 64 * SQS;         // [64][SQS] key-major
    uint32_t* sV = sK + 64 * SQS;         // [64][SVS] key-major
    uint32_t* sP = sV + 64 * SVS;         // [64][SPS]

    const int tid = threadIdx.x, lane = tid & 31, w = tid >> 5;
    const int g = lane >> 2, t = lane & 3;
    const int qt = blockIdx.x, h = blockIdx.y, b = blockIdx.z;
    const int q0 = w * 16;

    // stage Q once (scale folded in, tf32-rounded)
    {
        const int r = tid >> 1, d0 = (tid & 1) * 128;
        const float* qp = Qn + (((size_t)(b * SEQ + qt * 64 + r)) * NUM_HEADS + h) * QK_DIM + d0;
        uint32_t* dst = sQ + r * SQS + d0;
        const float sc = 0.0625f;   // 1/sqrt(2*HEAD_DIM)
#pragma unroll
        for (int j = 0; j < 32; j++) {
            float4 v = *(const float4*)(qp + j * 4);
            *(uint4*)(dst + j * 4) =
                make_uint4(f2tf(v.x * sc), f2tf(v.y * sc), f2tf(v.z * sc), f2tf(v.w * sc));
        }
    }

    float oacc[16][4];
#pragma unroll
    for (int dt = 0; dt < 16; dt++)
#pragma unroll
        for (int e = 0; e < 4; e++) oacc[dt][e] = 0.f;
    float mA = -3e38f, mB = -3e38f, lA = 0.f, lB = 0.f;

    for (int kt = 0; kt <= qt; kt++) {
        // stage K (64x256) + V (64x128), tf32-rounded
        {
            const int r = tid >> 1, d0 = (tid & 1) * 128;
            const float* kp = Kn + (((size_t)(b * SEQ + kt * 64 + r)) * NUM_HEADS + h) * QK_DIM + d0;
            uint32_t* kd = sK + r * SQS + d0;
#pragma unroll
            for (int j = 0; j < 32; j++) {
                float4 v = *(const float4*)(kp + j * 4);
                *(uint4*)(kd + j * 4) = make_uint4(f2tf(v.x), f2tf(v.y), f2tf(v.z), f2tf(v.w));
            }
            const int vd0 = (tid & 1) * 64;
            const float* vp = Vp + (size_t)(b * SEQ + kt * 64 + r) * D_MODEL + h * HEAD_DIM + vd0;
            uint32_t* vd = sV + r * SVS + vd0;
#pragma unroll
            for (int j = 0; j < 16; j++) {
                float4 v = *(const float4*)(vp + j * 4);
                *(uint4*)(vd + j * 4) = make_uint4(f2tf(v.x), f2tf(v.y), f2tf(v.z), f2tf(v.w));
            }
        }
        __syncthreads();

        // S = Q @ K^T  (warp: 16 q-rows x 64 keys)
        float sacc[8][4];
#pragma unroll
        for (int j = 0; j < 8; j++)
#pragma unroll
            for (int e = 0; e < 4; e++) sacc[j][e] = 0.f;
        const uint32_t* qA = sQ + (q0 + g) * SQS;
        const uint32_t* qB = qA + 8 * SQS;
#pragma unroll 2
        for (int d0 = 0; d0 < QK_DIM; d0 += 8) {
            uint32_t a0 = qA[d0 + t], a1 = qB[d0 + t];
            uint32_t a2 = qA[d0 + t + 4], a3 = qB[d0 + t + 4];
#pragma unroll
            for (int j = 0; j < 8; j++) {
                const uint32_t* kr = sK + (j * 8 + g) * SQS + d0;
                mma8(sacc[j], a0, a1, a2, a3, kr[t], kr[t + 4]);
            }
        }

        if (kt == qt) {   // causal mask on the diagonal tile
#pragma unroll
            for (int j = 0; j < 8; j++) {
                int c0 = j * 8 + 2 * t;
                if (c0     > q0 + g)     sacc[j][0] = -3e38f;
                if (c0 + 1 > q0 + g)     sacc[j][1] = -3e38f;
                if (c0     > q0 + g + 8) sacc[j][2] = -3e38f;
                if (c0 + 1 > q0 + g + 8) sacc[j][3] = -3e38f;
            }
        }

        // online softmax (warp-local; rows owned by quads)
        float rmA = -3e38f, rmB = -3e38f;
#pragma unroll
        for (int j = 0; j < 8; j++) {
            rmA = fmaxf(rmA, fmaxf(sacc[j][0], sacc[j][1]));
            rmB = fmaxf(rmB, fmaxf(sacc[j][2], sacc[j][3]));
        }
        rmA = fmaxf(rmA, __shfl_xor_sync(0xffffffffu, rmA, 1));
        rmA = fmaxf(rmA, __shfl_xor_sync(0xffffffffu, rmA, 2));
        rmB = fmaxf(rmB, __shfl_xor_sync(0xffffffffu, rmB, 1));
        rmB = fmaxf(rmB, __shfl_xor_sync(0xffffffffu, rmB, 2));
        float mnA = fmaxf(mA, rmA), mnB = fmaxf(mB, rmB);
        float aAl = fast_exp(mA - mnA), aBl = fast_exp(mB - mnB);
        mA = mnA; mB = mnB;

        float lsA = 0.f, lsB = 0.f;
        uint32_t* pA = sP + (q0 + g) * SPS;
        uint32_t* pB = pA + 8 * SPS;
#pragma unroll
        for (int j = 0; j < 8; j++) {
            uint32_t p0 = f2tf(fast_exp(sacc[j][0] - mnA));
            uint32_t p1 = f2tf(fast_exp(sacc[j][1] - mnA));
            uint32_t p2 = f2tf(fast_exp(sacc[j][2] - mnB));
            uint32_t p3 = f2tf(fast_exp(sacc[j][3] - mnB));
            lsA += __uint_as_float(p0) + __uint_as_float(p1);
            lsB += __uint_as_float(p2) + __uint_as_float(p3);
            pA[j * 8 + 2 * t] = p0; pA[j * 8 + 2 * t + 1] = p1;
            pB[j * 8 + 2 * t] = p2; pB[j * 8 + 2 * t + 1] = p3;
        }
        lsA += __shfl_xor_sync(0xffffffffu, lsA, 1);
        lsA += __shfl_xor_sync(0xffffffffu, lsA, 2);
        lsB += __shfl_xor_sync(0xffffffffu, lsB, 1);
        lsB += __shfl_xor_sync(0xffffffffu, lsB, 2);
        lA = lA * aAl + lsA;
        lB = lB * aBl + lsB;

#pragma unroll
        for (int dt = 0; dt < 16; dt++) {
            oacc[dt][0] *= aAl; oacc[dt][1] *= aAl;
            oacc[dt][2] *= aBl; oacc[dt][3] *= aBl;
        }
        __syncwarp();

        // O += P @ V  (warp: 16 rows x 128 d)
#pragma unroll
        for (int k0 = 0; k0 < 64; k0 += 8) {
            uint32_t a0 = pA[k0 + t], a1 = pB[k0 + t];
            uint32_t a2 = pA[k0 + t + 4], a3 = pB[k0 + t + 4];
            const uint32_t* v0r = sV + (k0 + t) * SVS + g;
            const uint32_t* v1r = sV + (k0 + t + 4) * SVS + g;
#pragma unroll
            for (int dt = 0; dt < 16; dt++)
                mma8(oacc[dt], a0, a1, a2, a3, v0r[dt * 8], v1r[dt * 8]);
        }
        __syncthreads();
    }

    // normalize + write
    float iA = 1.f / lA, iB = 1.f / lB;
    float* oA = Op + ((size_t)(b * SEQ + qt * 64 + q0 + g)) * D_MODEL + h * HEAD_DIM;
    float* oB = oA + (size_t)8 * D_MODEL;
#pragma unroll
    for (int dt = 0; dt < 16; dt++) {
        int c = dt * 8 + 2 * t;
        *(float2*)(oA + c) = make_float2(oacc[dt][0] * iA, oacc[dt][1] * iA);
        *(float2*)(oB + c) = make_float2(oacc[dt][2] * iB, oacc[dt][3] * iB);
    }
}

// ---------------------------------------------------------------------------
extern "C" void kernel_launch(void* const* d_in, const int* in_sizes, int n_in,
                              void* d_out, int out_size)
{
    const float* inq  = (const float*)d_in[0];
    const float* ink  = (const float*)d_in[1];
    const float* Wqd  = (const float*)d_in[3];
    const float* Wkvd = (const float*)d_in[4];
    const float* Wqu  = (const float*)d_in[5];
    const float* Wku  = (const float*)d_in[6];
    const float* Wvu  = (const float*)d_in[7];
    const float* Wqr  = (const float*)d_in[8];
    const float* Wkr  = (const float*)d_in[9];
    const float* Wo   = (const float*)d_in[10];
    const float* bo   = (const float*)d_in[11];
    float* out = (float*)d_out;

    float *qlat, *kvlat, *qnew, *knew, *vbuf, *attn, *qrt, *krt;
    cudaGetSymbolAddress((void**)&qlat,  g_qlat);
    cudaGetSymbolAddress((void**)&kvlat, g_kvlat);
    cudaGetSymbolAddress((void**)&qnew,  g_qnew);
    cudaGetSymbolAddress((void**)&knew,  g_knew);
    cudaGetSymbolAddress((void**)&vbuf,  g_v);
    cudaGetSymbolAddress((void**)&attn,  g_attn);
    cudaGetSymbolAddress((void**)&qrt,   g_qrt);
    cudaGetSymbolAddress((void**)&krt,   g_krt);

    // 1) q_latent = inputs_q @ Wq_down
    tf32gemm<<<dim3(Q_LATD / 128, ROWS / 128), 256>>>(
        inq, Wqd, qlat, nullptr, ROWS, Q_LATD, D_MODEL, Q_LATD, Q_LATD, 0, 0);
    // 2) kv_latent = inputs_k @ Wkv_down
    tf32gemm<<<dim3(KV_LATD / 128, ROWS / 128), 256>>>(
        ink, Wkvd, kvlat, nullptr, ROWS, KV_LATD, D_MODEL, KV_LATD, KV_LATD, 0, 0);
    // 3) q_proj -> q_new[..., 0:128] (head-interleaved)
    tf32gemm<<<dim3(D_MODEL / 128, ROWS / 128), 256>>>(
        qlat, Wqu, qnew, nullptr, ROWS, D_MODEL, Q_LATD, 4096, 128, 256, 0);
    // 4) q_rope pre-projection
    tf32gemm<<<dim3(D_MODEL / 128, ROWS / 128), 256>>>(
        qlat, Wqr, qrt, nullptr, ROWS, D_MODEL, Q_LATD, D_MODEL, D_MODEL, 0, 0);
    // 5) rope(q) -> q_new[..., 128:256]
    rope_q_kernel<<<dim3(4, ROWS), 256>>>(qrt, qnew);
    // 6) k_proj -> k_new[..., 0:128]
    tf32gemm<<<dim3(D_MODEL / 128, ROWS / 128), 256>>>(
        kvlat, Wku, knew, nullptr, ROWS, D_MODEL, KV_LATD, 4096, 128, 256, 0);
    // 7) v_proj
    tf32gemm<<<dim3(D_MODEL / 128, ROWS / 128), 256>>>(
        kvlat, Wvu, vbuf, nullptr, ROWS, D_MODEL, KV_LATD, D_MODEL, D_MODEL, 0, 0);
    // 8) k_rope pre-projection
    tf32gemm<<<dim3(HEAD_DIM / 128, ROWS / 128), 256>>>(
        ink, Wkr, krt, nullptr, ROWS, HEAD_DIM, D_MODEL, HEAD_DIM, HEAD_DIM, 0, 0);
    // 9) rope(k) + broadcast -> k_new[..., 128:256]
    rope_k_kernel<<<ROWS, 64>>>(krt, knew);

    // 10) causal flash attention (tf32 tensor cores)
    cudaFuncSetAttribute(mla_attn_tf32,
                         cudaFuncAttributeMaxDynamicSharedMemorySize, ATT_SMEM_BYTES);
    mla_attn_tf32<<<dim3(SEQ / 64, NUM_HEADS, BATCH), 128, ATT_SMEM_BYTES>>>(
        qnew, knew, vbuf, attn);

    // 11) final projection + bias
    tf32gemm<<<dim3(D_MODEL / 128, ROWS / 128), 256>>>(
        attn, Wo, out, bo, ROWS, D_MODEL, D_MODEL, D_MODEL, D_MODEL, 0, 0);
}

// round 4
// speedup vs baseline: 2.4110x; 1.1496x over previous
#include <cuda_runtime.h>
#include <math.h>
#include <stdint.h>

#define D_MODEL   2048
#define Q_LATD    1536
#define KV_LATD   512
#define NUM_HEADS 16
#define HEAD_DIM  128
#define BATCH     2
#define SEQ       2048
#define ROWS      (BATCH * SEQ)      // 4096
#define QK_DIM    256                // head_dim(128) + rope(128)

// ---------------- scratch (device globals; no allocation allowed) ----------
__device__ float g_qlat[ROWS * Q_LATD];
__device__ float g_kvlat[ROWS * KV_LATD];
__device__ float g_qnew[(size_t)ROWS * NUM_HEADS * QK_DIM];   // [b,s,h,256]
__device__ float g_knew[(size_t)ROWS * NUM_HEADS * QK_DIM];   // [b,s,h,256]
__device__ float g_v[(size_t)ROWS * D_MODEL];                 // [b,s,h*128]
__device__ float g_attn[(size_t)ROWS * D_MODEL];
__device__ float g_qrt[(size_t)ROWS * D_MODEL];
__device__ float g_krt[(size_t)ROWS * HEAD_DIM];

// ---------------- helpers --------------------------------------------------
__device__ __forceinline__ uint32_t f2tf(float x) {
    uint32_t u;
    asm("cvt.rna.tf32.f32 %0, %1;" : "=r"(u) : "f"(x));
    return u;
}

__device__ __forceinline__ uint32_t sptr(const void* p) {
    return (uint32_t)__cvta_generic_to_shared(p);
}

__device__ __forceinline__ void mma8(float c[4],
    uint32_t a0, uint32_t a1, uint32_t a2, uint32_t a3,
    uint32_t b0, uint32_t b1)
{
    asm volatile(
        "mma.sync.aligned.m16n8k8.row.col.f32.tf32.tf32.f32 "
        "{%0,%1,%2,%3}, {%4,%5,%6,%7}, {%8,%9}, {%0,%1,%2,%3};\n"
        : "+f"(c[0]), "+f"(c[1]), "+f"(c[2]), "+f"(c[3])
        : "r"(a0), "r"(a1), "r"(a2), "r"(a3), "r"(b0), "r"(b1));
}

__device__ __forceinline__ void ldmx4(uint32_t a[4], uint32_t addr) {
    asm volatile(
        "ldmatrix.sync.aligned.m8n8.x4.shared.b16 {%0,%1,%2,%3}, [%4];"
        : "=r"(a[0]), "=r"(a[1]), "=r"(a[2]), "=r"(a[3]) : "r"(addr));
}

#define CP16(dst, src) \
    asm volatile("cp.async.cg.shared.global [%0], [%1], 16;" :: "r"(dst), "l"(src))
#define CP_COMMIT() asm volatile("cp.async.commit_group;" ::: "memory")
#define CP_WAIT0()  asm volatile("cp.async.wait_group 0;" ::: "memory")
#define CP_WAIT1()  asm volatile("cp.async.wait_group 1;" ::: "memory")

// exp(x) for x <= 0 on the FMA pipe only (no MUFU)
__device__ __forceinline__ float fast_exp(float x) {
    float y  = fmaxf(x * 1.4426950408889634f, -126.0f);
    float tb = y + 12582912.0f;
    float nf = tb - 12582912.0f;
    float u  = (y - nf) * 0.6931471805599453f;
    float p  = fmaf(u, 0.008333334f, 0.041666668f);
    p = fmaf(p, u, 0.16666667f);
    p = fmaf(p, u, 0.5f);
    p = fmaf(p, u, 1.0f);
    p = fmaf(p, u, 1.0f);
    return p * __int_as_float(((int)nf + 127) << 23);
}

// ---------------- tf32 GEMM: C[M,N] = A[M,K] @ B[K,N] ----------------------
// block 128x128, BK=16, 256 thr / 8 warps, warp tile 64x32, double-buffered.
// A frags via ldmatrix (plain [m][20] layout). B frags scalar ([k][136]).
// Epilogue col remap: oc = (c/group)*gstride + c%group + goff; bias; rnd.
__global__ void __launch_bounds__(256, 2) tf32gemm(
    const float* __restrict__ A, const float* __restrict__ B,
    float* __restrict__ C, const float* __restrict__ bias,
    int M, int N, int K, int ldc, int group, int gstride, int goff, int rnd)
{
    __shared__ uint32_t As[2][128 * 20];   // [m][k] rows of 16 + pad4
    __shared__ uint32_t Bs[2][16 * 136];   // [k][n]

    const int tid  = threadIdx.x;
    const int lane = tid & 31, w = tid >> 5;
    const int g = lane >> 2, t = lane & 3;
    const int wm = (w & 1) * 64, wn = (w >> 1) * 32;
    const int bm = blockIdx.y * 128, bn = blockIdx.x * 128;

    const int am = tid >> 1, ak = (tid & 1) * 8;
    const int bk = tid >> 4, bn0 = (tid & 15) * 8;
    const float* Ag = A + (size_t)(bm + am) * K + ak;
    const float* Bg = B + (size_t)bk * N + bn + bn0;

    // per-lane ldmatrix base: row = wm + (lane&15), col = (lane>>4)*4
    const uint32_t aAddr = sptr(&As[0][0]) +
        (((wm + (lane & 15)) * 20 + ((lane >> 4) << 2)) << 2);

    float acc[4][4][4];
#pragma unroll
    for (int i = 0; i < 4; i++)
#pragma unroll
        for (int j = 0; j < 4; j++)
#pragma unroll
            for (int e = 0; e < 4; e++) acc[i][j][e] = 0.f;

    const int nk = K >> 4;

    float4 ra0 = *(const float4*)Ag;
    float4 ra1 = *(const float4*)(Ag + 4);
    float4 rb0 = *(const float4*)Bg;
    float4 rb1 = *(const float4*)(Bg + 4);

    *(uint4*)&As[0][am * 20 + ak] =
        make_uint4(f2tf(ra0.x), f2tf(ra0.y), f2tf(ra0.z), f2tf(ra0.w));
    *(uint4*)&As[0][am * 20 + ak + 4] =
        make_uint4(f2tf(ra1.x), f2tf(ra1.y), f2tf(ra1.z), f2tf(ra1.w));
    *(uint4*)&Bs[0][bk * 136 + bn0] =
        make_uint4(f2tf(rb0.x), f2tf(rb0.y), f2tf(rb0.z), f2tf(rb0.w));
    *(uint4*)&Bs[0][bk * 136 + bn0 + 4] =
        make_uint4(f2tf(rb1.x), f2tf(rb1.y), f2tf(rb1.z), f2tf(rb1.w));

    if (nk > 1) {
        ra0 = *(const float4*)(Ag + 16);
        ra1 = *(const float4*)(Ag + 20);
        rb0 = *(const float4*)(Bg + (size_t)16 * N);
        rb1 = *(const float4*)(Bg + (size_t)16 * N + 4);
    }
    __syncthreads();

    for (int kt = 0; kt < nk; kt++) {
        const int cur = kt & 1;
        const uint32_t aS = aAddr + cur * 10240;
#pragma unroll
        for (int ks = 0; ks < 2; ks++) {
            const int k0 = ks * 8;
            uint32_t af[4][4], bf[4][2];
#pragma unroll
            for (int mt = 0; mt < 4; mt++)
                ldmx4(af[mt], aS + mt * 1280 + ks * 32);
#pragma unroll
            for (int nt = 0; nt < 4; nt++) {
                const int n = wn + nt * 8 + g;
                bf[nt][0] = Bs[cur][(k0 + t) * 136 + n];
                bf[nt][1] = Bs[cur][(k0 + t + 4) * 136 + n];
            }
#pragma unroll
            for (int mt = 0; mt < 4; mt++)
#pragma unroll
                for (int nt = 0; nt < 4; nt++)
                    mma8(acc[mt][nt], af[mt][0], af[mt][1], af[mt][2], af[mt][3],
                         bf[nt][0], bf[nt][1]);
        }
        if (kt + 1 < nk) {
            const int nxt = cur ^ 1;
            *(uint4*)&As[nxt][am * 20 + ak] =
                make_uint4(f2tf(ra0.x), f2tf(ra0.y), f2tf(ra0.z), f2tf(ra0.w));
            *(uint4*)&As[nxt][am * 20 + ak + 4] =
                make_uint4(f2tf(ra1.x), f2tf(ra1.y), f2tf(ra1.z), f2tf(ra1.w));
            *(uint4*)&Bs[nxt][bk * 136 + bn0] =
                make_uint4(f2tf(rb0.x), f2tf(rb0.y), f2tf(rb0.z), f2tf(rb0.w));
            *(uint4*)&Bs[nxt][bk * 136 + bn0 + 4] =
                make_uint4(f2tf(rb1.x), f2tf(rb1.y), f2tf(rb1.z), f2tf(rb1.w));
            if (kt + 2 < nk) {
                const float* Ap = Ag + (kt + 2) * 16;
                ra0 = *(const float4*)Ap;
                ra1 = *(const float4*)(Ap + 4);
                const float* Bp = Bg + (size_t)(kt + 2) * 16 * N;
                rb0 = *(const float4*)Bp;
                rb1 = *(const float4*)(Bp + 4);
            }
        }
        __syncthreads();
    }

#pragma unroll
    for (int mt = 0; mt < 4; mt++) {
#pragma unroll
        for (int nt = 0; nt < 4; nt++) {
            const int r = bm + wm + mt * 16 + g;
            const int c = bn + wn + nt * 8 + 2 * t;
#pragma unroll
            for (int e = 0; e < 4; e++) {
                const int rr = r + ((e >> 1) << 3);
                const int cc = c + (e & 1);
                float v = acc[mt][nt][e];
                if (bias) v += bias[cc];
                if (rnd) v = __uint_as_float(f2tf(v));
                const int oc = (cc / group) * gstride + (cc % group) + goff;
                C[(size_t)rr * ldc + oc] = v;
            }
        }
    }
}

// ---------------- rope on q (full 2048 dims) -> q_new[...,128:256] ---------
__global__ void rope_q_kernel(const float* __restrict__ in, float* __restrict__ qnew)
{
    int j = blockIdx.x * blockDim.x + threadIdx.x;
    int row = blockIdx.y;
    if (j >= 1024) return;
    int pos = row & (SEQ - 1);
    float inv = powf(10000.0f, -(float)j * (1.0f / 1024.0f));
    float ang = (float)pos * inv;
    float sn, cs;
    sincosf(ang, &sn, &cs);
    float x1 = in[(size_t)row * 2048 + j];
    float x2 = in[(size_t)row * 2048 + j + 1024];
    float o1 = __uint_as_float(f2tf(x1 * cs - x2 * sn));
    float o2 = __uint_as_float(f2tf(x2 * cs + x1 * sn));
    int c1 = j, c2 = j + 1024;
    qnew[(size_t)row * 4096 + (c1 >> 7) * 256 + (c1 & 127) + 128] = o1;
    qnew[(size_t)row * 4096 + (c2 >> 7) * 256 + (c2 & 127) + 128] = o2;
}

// ---------------- rope on k (128 dims) + broadcast to all 16 heads ---------
__global__ void rope_k_kernel(const float* __restrict__ in, float* __restrict__ knew)
{
    int j = threadIdx.x;
    int row = blockIdx.x;
    int pos = row & (SEQ - 1);
    float inv = powf(10000.0f, -(float)j * (1.0f / 64.0f));
    float ang = (float)pos * inv;
    float sn, cs;
    sincosf(ang, &sn, &cs);
    float x1 = in[(size_t)row * 128 + j];
    float x2 = in[(size_t)row * 128 + j + 64];
    float o1 = __uint_as_float(f2tf(x1 * cs - x2 * sn));
    float o2 = __uint_as_float(f2tf(x2 * cs + x1 * sn));
    float* base = knew + (size_t)row * 4096 + 128;
#pragma unroll
    for (int h = 0; h < NUM_HEADS; h++) {
        base[h * 256 + j]      = o1;
        base[h * 256 + j + 64] = o2;
    }
}

// ---------------- flash attention v3 ---------------------------------------
// Bq=128 (8 warps x 16 rows), Bk=16, cp.async double-buffered K/V,
// Q/P frags via ldmatrix, K/V frags scalar (conflict-free strides).
#define BQ  128
#define BK  16
#define SQS 260   // 260 % 32 == 4
#define SKS 260
#define SVS 132   // 132 % 32 == 4
#define SPS 36    // 36  % 32 == 4
#define ATT_SMEM_BYTES ((BQ * SQS + 2 * BK * SKS + 2 * BK * SVS + BQ * SPS) * 4)

__global__ void __launch_bounds__(256, 1) mla_attn_tf32(
    const float* __restrict__ Qn, const float* __restrict__ Kn,
    const float* __restrict__ Vp, float* __restrict__ Op)
{
    extern __shared__ uint32_t sw[];
    uint32_t* sQ = sw;                         // [128][260]
    uint32_t* sK = sQ + BQ * SQS;              // [2][16][260]
    uint32_t* sV = sK + 2 * BK * SKS;          // [2][16][132]
    uint32_t* sP = sV + 2 * BK * SVS;          // [128][36]

    const int tid = threadIdx.x, lane = tid & 31, w = tid >> 5;
    const int g = lane >> 2, t = lane & 3;
    const int qt = blockIdx.x, h = blockIdx.y, b = blockIdx.z;
    const int q0 = w * 16;

    const uint32_t qAddr = sptr(sQ) +
        (((q0 + (lane & 15)) * SQS + ((lane >> 4) << 2)) << 2);
    const uint32_t pAddr = sptr(sP) +
        (((q0 + (lane & 15)) * SPS + ((lane >> 4) << 2)) << 2);

    const int sr  = tid >> 4;        // staging row 0..15
    const int seg = tid & 15;        // staging segment

    // prefetch tile 0
    {
        const float* kp = Kn + (((size_t)(b * SEQ + sr)) * NUM_HEADS + h) * QK_DIM + seg * 16;
        uint32_t kd = sptr(sK) + ((sr * SKS + seg * 16) << 2);
#pragma unroll
        for (int j = 0; j < 4; j++) CP16(kd + j * 16, kp + j * 4);
        const float* vp = Vp + ((size_t)(b * SEQ + sr)) * D_MODEL + h * HEAD_DIM + seg * 8;
        uint32_t vd = sptr(sV) + ((sr * SVS + seg * 8) << 2);
#pragma unroll
        for (int j = 0; j < 2; j++) CP16(vd + j * 16, vp + j * 4);
        CP_COMMIT();
    }

    // stage Q (pre-rounded input; scale by exact power of 2)
    {
        const int r = tid >> 1, d0 = (tid & 1) * 128;
        const float* qp = Qn + (((size_t)(b * SEQ + qt * BQ + r)) * NUM_HEADS + h) * QK_DIM + d0;
        uint32_t* dst = sQ + r * SQS + d0;
        const float sc = 0.0625f;   // 1/sqrt(2*HEAD_DIM) = 2^-4, exact
#pragma unroll
        for (int j = 0; j < 32; j++) {
            float4 v = *(const float4*)(qp + j * 4);
            *(uint4*)(dst + j * 4) = make_uint4(
                __float_as_uint(v.x * sc), __float_as_uint(v.y * sc),
                __float_as_uint(v.z * sc), __float_as_uint(v.w * sc));
        }
    }

    float oacc[16][4];
#pragma unroll
    for (int dt = 0; dt < 16; dt++)
#pragma unroll
        for (int e = 0; e < 4; e++) oacc[dt][e] = 0.f;
    float mA = -3e38f, mB = -3e38f, lA = 0.f, lB = 0.f;

    const int ntiles = 8 * qt + 8;
    for (int tt = 0; tt < ntiles; tt++) {
        if (tt + 1 < ntiles) {   // prefetch next tile into other buffer
            const int buf = (tt + 1) & 1;
            const float* kp = Kn + (((size_t)(b * SEQ + (tt + 1) * BK + sr)) * NUM_HEADS + h) * QK_DIM + seg * 16;
            uint32_t kd = sptr(sK) + ((buf * BK * SKS + sr * SKS + seg * 16) << 2);
#pragma unroll
            for (int j = 0; j < 4; j++) CP16(kd + j * 16, kp + j * 4);
            const float* vp = Vp + ((size_t)(b * SEQ + (tt + 1) * BK + sr)) * D_MODEL + h * HEAD_DIM + seg * 8;
            uint32_t vd = sptr(sV) + ((buf * BK * SVS + sr * SVS + seg * 8) << 2);
#pragma unroll
            for (int j = 0; j < 2; j++) CP16(vd + j * 16, vp + j * 4);
            CP_COMMIT();
            CP_WAIT1();
        } else {
            CP_WAIT0();
        }
        __syncthreads();

        const uint32_t* sKb = sK + (tt & 1) * BK * SKS;
        const uint32_t* sVb = sV + (tt & 1) * BK * SVS;

        // S = Q @ K^T (16 q-rows x 16 keys per warp)
        float sacc[2][4];
#pragma unroll
        for (int j = 0; j < 2; j++)
#pragma unroll
            for (int e = 0; e < 4; e++) sacc[j][e] = 0.f;
#pragma unroll 8
        for (int d0 = 0; d0 < QK_DIM; d0 += 8) {
            uint32_t a[4];
            ldmx4(a, qAddr + d0 * 4);
#pragma unroll
            for (int j = 0; j < 2; j++) {
                const uint32_t* kr = sKb + (j * 8 + g) * SKS + d0;
                mma8(sacc[j], a[0], a[1], a[2], a[3], kr[t], kr[t + 4]);
            }
        }

        if (tt >= 8 * qt) {   // diagonal-region masking
            const int kb = tt * BK + 2 * t;
            const int qA = qt * BQ + q0 + g, qB = qA + 8;
#pragma unroll
            for (int j = 0; j < 2; j++) {
                int k0g = kb + j * 8;
                if (k0g     > qA) sacc[j][0] = -3e38f;
                if (k0g + 1 > qA) sacc[j][1] = -3e38f;
                if (k0g     > qB) sacc[j][2] = -3e38f;
                if (k0g + 1 > qB) sacc[j][3] = -3e38f;
            }
        }

        // online softmax (rows owned by quads)
        float rmA = fmaxf(fmaxf(sacc[0][0], sacc[0][1]), fmaxf(sacc[1][0], sacc[1][1]));
        float rmB = fmaxf(fmaxf(sacc[0][2], sacc[0][3]), fmaxf(sacc[1][2], sacc[1][3]));
        rmA = fmaxf(rmA, __shfl_xor_sync(0xffffffffu, rmA, 1));
        rmA = fmaxf(rmA, __shfl_xor_sync(0xffffffffu, rmA, 2));
        rmB = fmaxf(rmB, __shfl_xor_sync(0xffffffffu, rmB, 1));
        rmB = fmaxf(rmB, __shfl_xor_sync(0xffffffffu, rmB, 2));
        float mnA = fmaxf(mA, rmA), mnB = fmaxf(mB, rmB);
        float aAl = fast_exp(mA - mnA), aBl = fast_exp(mB - mnB);
        mA = mnA; mB = mnB;

        float lsA = 0.f, lsB = 0.f;
        uint32_t* pA = sP + (q0 + g) * SPS;
        uint32_t* pB = pA + 8 * SPS;
#pragma unroll
        for (int j = 0; j < 2; j++) {
            uint32_t p0 = f2tf(fast_exp(sacc[j][0] - mnA));
            uint32_t p1 = f2tf(fast_exp(sacc[j][1] - mnA));
            uint32_t p2 = f2tf(fast_exp(sacc[j][2] - mnB));
            uint32_t p3 = f2tf(fast_exp(sacc[j][3] - mnB));
            lsA += __uint_as_float(p0) + __uint_as_float(p1);
            lsB += __uint_as_float(p2) + __uint_as_float(p3);
            pA[j * 8 + 2 * t] = p0; pA[j * 8 + 2 * t + 1] = p1;
            pB[j * 8 + 2 * t] = p2; pB[j * 8 + 2 * t + 1] = p3;
        }
        lsA += __shfl_xor_sync(0xffffffffu, lsA, 1);
        lsA += __shfl_xor_sync(0xffffffffu, lsA, 2);
        lsB += __shfl_xor_sync(0xffffffffu, lsB, 1);
        lsB += __shfl_xor_sync(0xffffffffu, lsB, 2);
        lA = lA * aAl + lsA;
        lB = lB * aBl + lsB;

#pragma unroll
        for (int dt = 0; dt < 16; dt++) {
            oacc[dt][0] *= aAl; oacc[dt][1] *= aAl;
            oacc[dt][2] *= aBl; oacc[dt][3] *= aBl;
        }
        __syncwarp();

        // O += P @ V
#pragma unroll
        for (int k0 = 0; k0 < BK; k0 += 8) {
            uint32_t p[4];
            ldmx4(p, pAddr + k0 * 4);
            const uint32_t* v0r = sVb + (k0 + t) * SVS + g;
            const uint32_t* v1r = sVb + (k0 + t + 4) * SVS + g;
#pragma unroll
            for (int dt = 0; dt < 16; dt++)
                mma8(oacc[dt], p[0], p[1], p[2], p[3], v0r[dt * 8], v1r[dt * 8]);
        }
        __syncthreads();
    }

    // normalize + write
    float iA = 1.f / lA, iB = 1.f / lB;
    float* oA = Op + ((size_t)(b * SEQ + qt * BQ + q0 + g)) * D_MODEL + h * HEAD_DIM;
    float* oB = oA + (size_t)8 * D_MODEL;
#pragma unroll
    for (int dt = 0; dt < 16; dt++) {
        int c = dt * 8 + 2 * t;
        *(float2*)(oA + c) = make_float2(oacc[dt][0] * iA, oacc[dt][1] * iA);
        *(float2*)(oB + c) = make_float2(oacc[dt][2] * iB, oacc[dt][3] * iB);
    }
}

// ---------------------------------------------------------------------------
extern "C" void kernel_launch(void* const* d_in, const int* in_sizes, int n_in,
                              void* d_out, int out_size)
{
    const float* inq  = (const float*)d_in[0];
    const float* ink  = (const float*)d_in[1];
    const float* Wqd  = (const float*)d_in[3];
    const float* Wkvd = (const float*)d_in[4];
    const float* Wqu  = (const float*)d_in[5];
    const float* Wku  = (const float*)d_in[6];
    const float* Wvu  = (const float*)d_in[7];
    const float* Wqr  = (const float*)d_in[8];
    const float* Wkr  = (const float*)d_in[9];
    const float* Wo   = (const float*)d_in[10];
    const float* bo   = (const float*)d_in[11];
    float* out = (float*)d_out;

    float *qlat, *kvlat, *qnew, *knew, *vbuf, *attn, *qrt, *krt;
    cudaGetSymbolAddress((void**)&qlat,  g_qlat);
    cudaGetSymbolAddress((void**)&kvlat, g_kvlat);
    cudaGetSymbolAddress((void**)&qnew,  g_qnew);
    cudaGetSymbolAddress((void**)&knew,  g_knew);
    cudaGetSymbolAddress((void**)&vbuf,  g_v);
    cudaGetSymbolAddress((void**)&attn,  g_attn);
    cudaGetSymbolAddress((void**)&qrt,   g_qrt);
    cudaGetSymbolAddress((void**)&krt,   g_krt);

    // 1) q_latent = inputs_q @ Wq_down
    tf32gemm<<<dim3(Q_LATD / 128, ROWS / 128), 256>>>(
        inq, Wqd, qlat, nullptr, ROWS, Q_LATD, D_MODEL, Q_LATD, Q_LATD, 0, 0, 1);
    // 2) kv_latent = inputs_k @ Wkv_down
    tf32gemm<<<dim3(KV_LATD / 128, ROWS / 128), 256>>>(
        ink, Wkvd, kvlat, nullptr, ROWS, KV_LATD, D_MODEL, KV_LATD, KV_LATD, 0, 0, 1);
    // 3) q_proj -> q_new[..., 0:128] (head-interleaved, rounded)
    tf32gemm<<<dim3(D_MODEL / 128, ROWS / 128), 256>>>(
        qlat, Wqu, qnew, nullptr, ROWS, D_MODEL, Q_LATD, 4096, 128, 256, 0, 1);
    // 4) q_rope pre-projection
    tf32gemm<<<dim3(D_MODEL / 128, ROWS / 128), 256>>>(
        qlat, Wqr, qrt, nullptr, ROWS, D_MODEL, Q_LATD, D_MODEL, D_MODEL, 0, 0, 1);
    // 5) rope(q) -> q_new[..., 128:256] (rounded)
    rope_q_kernel<<<dim3(4, ROWS), 256>>>(qrt, qnew);
    // 6) k_proj -> k_new[..., 0:128] (rounded)
    tf32gemm<<<dim3(D_MODEL / 128, ROWS / 128), 256>>>(
        kvlat, Wku, knew, nullptr, ROWS, D_MODEL, KV_LATD, 4096, 128, 256, 0, 1);
    // 7) v_proj (rounded)
    tf32gemm<<<dim3(D_MODEL / 128, ROWS / 128), 256>>>(
        kvlat, Wvu, vbuf, nullptr, ROWS, D_MODEL, KV_LATD, D_MODEL, D_MODEL, 0, 0, 1);
    // 8) k_rope pre-projection
    tf32gemm<<<dim3(HEAD_DIM / 128, ROWS / 128), 256>>>(
        ink, Wkr, krt, nullptr, ROWS, HEAD_DIM, D_MODEL, HEAD_DIM, HEAD_DIM, 0, 0, 1);
    // 9) rope(k) + broadcast -> k_new[..., 128:256] (rounded)
    rope_k_kernel<<<ROWS, 64>>>(krt, knew);

    // 10) causal flash attention (tf32, cp.async pipelined)
    cudaFuncSetAttribute(mla_attn_tf32,
                         cudaFuncAttributeMaxDynamicSharedMemorySize, ATT_SMEM_BYTES);
    mla_attn_tf32<<<dim3(SEQ / BQ, NUM_HEADS, BATCH), 256, ATT_SMEM_BYTES>>>(
        qnew, knew, vbuf, attn);

    // 11) final projection + bias (full precision out)
    tf32gemm<<<dim3(D_MODEL / 128, ROWS / 128), 256>>>(
        attn, Wo, out, bo, ROWS, D_MODEL, D_MODEL, D_MODEL, D_MODEL, 0, 0, 0);
}